// round 6
// baseline (speedup 1.0000x reference)
#include <cuda_runtime.h>

// MultiScaleRoIAlign: 4-level FPN, RoIAlign(aligned=False), OUT=7, SR=2.
// feats: [2,256,200,200],[2,256,100,100],[2,256,50,50],[2,256,25,25] fp32
// boxes: [2,256,4] fp32 -> out: [512,256,7,7] fp32
//
// One block (128 threads = 4 warps) per RoI. Each warp owns 64 channels
// end-to-end: cp.async-stage the RoI's bounding region for channel c into a
// warp-private smem buffer (double buffered), compute the 49 bins (lane->bin,
// separable bilinear, geometry hoisted to registers), store, advance.
// No __syncthreads in the hot loop -- only per-warp __syncwarp.

#define NLVL 4
#define MAXCELLS 1024
#define NW 4        // warps per block
#define CHPW 64     // channels per warp

__device__ __forceinline__ unsigned smem_u32(const void* p) {
    return (unsigned)__cvta_generic_to_shared(p);
}
__device__ __forceinline__ void cp_async4(unsigned dst, const float* src) {
    asm volatile("cp.async.ca.shared.global [%0], [%1], 4;\n" :: "r"(dst), "l"(src));
}
__device__ __forceinline__ void cp_commit() {
    asm volatile("cp.async.commit_group;\n" ::: "memory");
}
template <int N> __device__ __forceinline__ void cp_wait() {
    asm volatile("cp.async.wait_group %0;\n" :: "n"(N) : "memory");
}

__global__ __launch_bounds__(128) void roi_align_kernel(
    const float* __restrict__ f0, const float* __restrict__ f1,
    const float* __restrict__ f2, const float* __restrict__ f3,
    const float* __restrict__ boxes, float* __restrict__ out)
{
    const int r    = blockIdx.x;
    const int tid  = threadIdx.x;
    const int w    = tid >> 5;
    const int lane = tid & 31;
    const int b    = r >> 8;

    // ---- per-RoI geometry ----
    const float bx1 = boxes[r * 4 + 0];
    const float by1 = boxes[r * 4 + 1];
    const float bx2 = boxes[r * 4 + 2];
    const float by2 = boxes[r * 4 + 3];

    const float area = (bx2 - bx1) * (by2 - by1);
    float lv = floorf(4.0f + log2f(sqrtf(area) / 224.0f + 1e-6f));
    lv = fminf(fmaxf(lv, 2.0f), 5.0f);
    const int level = (int)lv - 2;

    const int   Htab[NLVL]  = {200, 100, 50, 25};
    const float sctab[NLVL] = {0.25f, 0.125f, 0.0625f, 0.03125f};
    const int   H  = Htab[level];
    const int   W  = H;
    const float sc = sctab[level];
    const float* feat = (level == 0) ? f0 : (level == 1) ? f1 : (level == 2) ? f2 : f3;

    const float x1 = bx1 * sc, y1 = by1 * sc;
    const float roi_w = fmaxf(bx2 * sc - x1, 1.0f);
    const float roi_h = fmaxf(by2 * sc - y1, 1.0f);
    const float bin_w = roi_w / 7.0f;
    const float bin_h = roi_h / 7.0f;

    // ---- smem ----
    __shared__ int   s_yl[14], s_yh[14], s_xl[14], s_xh[14];
    __shared__ float s_ly[14], s_lx[14], s_vy[14], s_vx[14];
    __shared__ int   gR[4][49], gX[4][49];
    __shared__ float gCy[4][49], gCx[4][49];
    __shared__ float s_buf[NW][2][MAXCELLS];   // 32 KB

    if (tid < 30) {
        const bool isx = (tid >= 16);
        const int  jj  = isx ? (tid - 16) : tid;
        if (jj < 14) {
            const int ph = jj >> 1;
            const int ii = jj & 1;
            const float g = (float)ph + ((float)ii + 0.5f) * 0.5f;
            float pos = isx ? (x1 + g * bin_w) : (y1 + g * bin_h);
            const float lim = (float)H;
            const float vld = (pos >= -1.0f && pos <= lim) ? 1.0f : 0.0f;
            pos = fmaxf(pos, 0.0f);
            int lo = (int)pos;
            int hi;
            if (lo >= H - 1) { lo = H - 1; hi = H - 1; pos = (float)lo; }
            else             { hi = lo + 1; }
            const float frac = pos - (float)lo;
            if (isx) { s_xl[jj] = lo; s_xh[jj] = hi; s_lx[jj] = frac; s_vx[jj] = vld; }
            else     { s_yl[jj] = lo; s_yh[jj] = hi; s_ly[jj] = frac; s_vy[jj] = vld; }
        }
    }
    __syncthreads();

    const int ry0 = s_yl[0], ry1 = s_yh[13];
    const int rx0 = s_xl[0], rx1 = s_xh[13];
    const int nrows = ry1 - ry0 + 1;
    const int ncols = rx1 - rx0 + 1;
    const int cells = nrows * ncols;

    const size_t plane = (size_t)H * W;

    if (cells <= MAXCELLS) {
        const float* fbase = feat + (size_t)b * 256 * plane + (size_t)ry0 * W + rx0;
        const int c0 = w * CHPW;

        float* sb0 = &s_buf[w][0][0];
        float* sb1 = &s_buf[w][1][0];

        // warp-private staging: lane -> column, loop rows (coalesced per row)
        auto stage = [&](int c, float* dst) {
            const float* fp = fbase + (size_t)c * plane;
            for (int row = 0; row < nrows; row++) {
                for (int col = lane; col < ncols; col += 32)
                    cp_async4(smem_u32(dst + col), fp + col);
                fp += W; dst += ncols;
            }
        };

        // prologue: stage first two channels of this warp
        stage(c0 + 0, sb0); cp_commit();
        stage(c0 + 1, sb1); cp_commit();

        // per-bin geometry table (overlaps with prologue LDG latency)
        if (tid < 49) {
            const int ph = tid / 7;
            const int pw = tid - ph * 7;
            #pragma unroll
            for (int s = 0; s < 2; s++) {
                const int jy = 2 * ph + s;
                const int jx = 2 * pw + s;
                const float vy = 0.25f * s_vy[jy];
                gR[2 * s + 0][tid] = (s_yl[jy] - ry0) * ncols;
                gR[2 * s + 1][tid] = (s_yh[jy] - ry0) * ncols;
                gCy[2 * s + 0][tid] = vy * (1.0f - s_ly[jy]);
                gCy[2 * s + 1][tid] = vy * s_ly[jy];
                gX[2 * s + 0][tid] = s_xl[jx] - rx0;
                gX[2 * s + 1][tid] = s_xh[jx] - rx0;
                gCx[2 * s + 0][tid] = s_vx[jx] * (1.0f - s_lx[jx]);
                gCx[2 * s + 1][tid] = s_vx[jx] * s_lx[jx];
            }
        }
        __syncthreads();   // table visible; last block-wide sync

        // hoist per-lane bin geometry (constant across all 64 channels)
        int Rr[2][4], Xx[2][4];
        float Cy[2][4], Cx[2][4];
        #pragma unroll
        for (int chk = 0; chk < 2; chk++) {
            const int bin = lane + 32 * chk;
            const int bb  = (bin < 49) ? bin : 0;
            #pragma unroll
            for (int i = 0; i < 4; i++) {
                Rr[chk][i] = gR[i][bb];
                Xx[chk][i] = gX[i][bb];
                Cy[chk][i] = gCy[i][bb];
                Cx[chk][i] = gCx[i][bb];
            }
        }

        float* op = out + ((size_t)r * 256 + c0) * 49;

        for (int k = 0; k < CHPW; k++) {
            cp_wait<1>();
            __syncwarp();
            const float* S = (k & 1) ? sb1 : sb0;

            // chk0: bins 0..31
            {
                float acc = 0.0f;
                #pragma unroll
                for (int i = 0; i < 4; i++) {
                    const float* A = S + Rr[0][i];
                    acc += Cy[0][i] * (Cx[0][0] * A[Xx[0][0]] + Cx[0][1] * A[Xx[0][1]]
                                     + Cx[0][2] * A[Xx[0][2]] + Cx[0][3] * A[Xx[0][3]]);
                }
                op[lane] = acc;
            }
            // chk1: bins 32..48
            if (lane < 17) {
                float acc = 0.0f;
                #pragma unroll
                for (int i = 0; i < 4; i++) {
                    const float* A = S + Rr[1][i];
                    acc += Cy[1][i] * (Cx[1][0] * A[Xx[1][0]] + Cx[1][1] * A[Xx[1][1]]
                                     + Cx[1][2] * A[Xx[1][2]] + Cx[1][3] * A[Xx[1][3]]);
                }
                op[32 + lane] = acc;
            }
            __syncwarp();   // WAR: all lanes done reading before restage

            if (k + 2 < CHPW)
                stage(c0 + k + 2, (k & 1) ? sb1 : sb0);
            cp_commit();
            op += 49;
        }
    } else {
        // ---- fallback (near-unreachable): direct gather, 2 channels/thread ----
        for (int c = tid; c < 256; c += 128) {
            const float* fp = feat + (size_t)(b * 256 + c) * plane;
            float* op = out + ((size_t)r * 256 + c) * 49;
            for (int ph = 0; ph < 7; ph++) {
                #pragma unroll
                for (int pw = 0; pw < 7; pw++) {
                    float acc = 0.0f;
                    #pragma unroll
                    for (int iy = 0; iy < 2; iy++) {
                        const int jy = 2 * ph + iy;
                        const float ly = s_ly[jy], hy = 1.0f - ly, vy = s_vy[jy];
                        const int ra = s_yl[jy] * W, rb = s_yh[jy] * W;
                        #pragma unroll
                        for (int ix = 0; ix < 2; ix++) {
                            const int jx = 2 * pw + ix;
                            const float lx = s_lx[jx], hx = 1.0f - lx, vx = s_vx[jx];
                            const int xl = s_xl[jx], xh = s_xh[jx];
                            const float bil = hy * (hx * fp[ra + xl] + lx * fp[ra + xh])
                                            + ly * (hx * fp[rb + xl] + lx * fp[rb + xh]);
                            acc += (vy * vx) * bil;
                        }
                    }
                    op[ph * 7 + pw] = acc * 0.25f;
                }
            }
        }
    }
}

extern "C" void kernel_launch(void* const* d_in, const int* in_sizes, int n_in,
                              void* d_out, int out_size) {
    const int nroi = in_sizes[4] / 4;   // 512
    roi_align_kernel<<<nroi, 128>>>(
        (const float*)d_in[0], (const float*)d_in[1],
        (const float*)d_in[2], (const float*)d_in[3],
        (const float*)d_in[4], (float*)d_out);
}

// round 7
// speedup vs baseline: 3.0476x; 3.0476x over previous
#include <cuda_runtime.h>

// MultiScaleRoIAlign: 4-level FPN, RoIAlign(aligned=False), OUT=7, SR=2.
// feats: [2,256,200,200],[2,256,100,100],[2,256,50,50],[2,256,25,25] fp32
// boxes: [2,256,4] fp32 -> out: [512,256,7,7] fp32
//
// v7: pure direct gather. One block (256 thr) per RoI; warp = channel,
// lane = bin (chunk0: bins 0..31, chunk1: bins 32..48). Per-lane bin
// geometry (row offsets, col offsets, separable weights incl. validity
// and the /4 sample mean) computed ONCE into registers; each warp then
// sweeps 32 channels with 32 independent LDGs + 40 FMAs per channel.
// No shared memory, no barriers.

#define NLVL 4

__global__ __launch_bounds__(256) void roi_align_kernel(
    const float* __restrict__ f0, const float* __restrict__ f1,
    const float* __restrict__ f2, const float* __restrict__ f3,
    const float* __restrict__ boxes, float* __restrict__ out)
{
    const int r    = blockIdx.x;     // roi 0..511
    const int tid  = threadIdx.x;
    const int w    = tid >> 5;       // warp 0..7
    const int lane = tid & 31;
    const int b    = r >> 8;

    // ---- per-RoI geometry ----
    const float bx1 = boxes[r * 4 + 0];
    const float by1 = boxes[r * 4 + 1];
    const float bx2 = boxes[r * 4 + 2];
    const float by2 = boxes[r * 4 + 3];

    const float area = (bx2 - bx1) * (by2 - by1);
    float lv = floorf(4.0f + log2f(sqrtf(area) / 224.0f + 1e-6f));
    lv = fminf(fmaxf(lv, 2.0f), 5.0f);
    const int level = (int)lv - 2;

    const int   Htab[NLVL]  = {200, 100, 50, 25};
    const float sctab[NLVL] = {0.25f, 0.125f, 0.0625f, 0.03125f};
    const int   H  = Htab[level];
    const int   W  = H;
    const float sc = sctab[level];
    const float* feat = (level == 0) ? f0 : (level == 1) ? f1 : (level == 2) ? f2 : f3;

    const float x1 = bx1 * sc, y1 = by1 * sc;
    const float roi_w = fmaxf(bx2 * sc - x1, 1.0f);
    const float roi_h = fmaxf(by2 * sc - y1, 1.0f);
    const float bin_w = roi_w / 7.0f;
    const float bin_h = roi_h / 7.0f;

    // ---- per-lane bin geometry, fully in registers ----
    // chunk 0: bin = lane; chunk 1: bin = lane + 32 (lanes >= 17 clamp to 0,
    // harmless duplicate loads, store is guarded).
    int   Ry[2][4], Xc[2][4];
    float Cy[2][4], Cx[2][4];

    #pragma unroll
    for (int chk = 0; chk < 2; chk++) {
        int bin = lane + 32 * chk;
        if (bin > 48) bin = 0;
        const int ph = bin / 7;            // const divisor -> mul/shift
        const int pw = bin - 7 * ph;

        #pragma unroll
        for (int s = 0; s < 2; s++) {
            // ---- y tap (jy = 2*ph + s) ----
            {
                const float g   = (float)ph + ((float)s + 0.5f) * 0.5f;
                float pos = y1 + g * bin_h;
                const float vld = (pos >= -1.0f && pos <= (float)H) ? 0.25f : 0.0f; // fold /4
                pos = fmaxf(pos, 0.0f);
                int lo = (int)pos, hi;
                if (lo >= H - 1) { lo = H - 1; hi = H - 1; pos = (float)lo; }
                else             { hi = lo + 1; }
                const float fr = pos - (float)lo;
                Ry[chk][2 * s + 0] = lo * W;
                Ry[chk][2 * s + 1] = hi * W;
                Cy[chk][2 * s + 0] = vld * (1.0f - fr);
                Cy[chk][2 * s + 1] = vld * fr;
            }
            // ---- x tap (jx = 2*pw + s) ----
            {
                const float g   = (float)pw + ((float)s + 0.5f) * 0.5f;
                float pos = x1 + g * bin_w;
                const float vld = (pos >= -1.0f && pos <= (float)W) ? 1.0f : 0.0f;
                pos = fmaxf(pos, 0.0f);
                int lo = (int)pos, hi;
                if (lo >= W - 1) { lo = W - 1; hi = W - 1; pos = (float)lo; }
                else             { hi = lo + 1; }
                const float fr = pos - (float)lo;
                Xc[chk][2 * s + 0] = lo;
                Xc[chk][2 * s + 1] = hi;
                Cx[chk][2 * s + 0] = vld * (1.0f - fr);
                Cx[chk][2 * s + 1] = vld * fr;
            }
        }
    }

    // ---- sweep 32 channels per warp ----
    const size_t plane = (size_t)H * W;
    const float* fp = feat + ((size_t)b * 256 + (size_t)w * 32) * plane;
    float* op = out + ((size_t)r * 256 + (size_t)w * 32) * 49;

    for (int k = 0; k < 32; k++) {
        float acc0 = 0.0f, acc1 = 0.0f;

        // chunk 0: bins 0..31
        #pragma unroll
        for (int i = 0; i < 4; i++) {
            const float* A = fp + Ry[0][i];
            acc0 += Cy[0][i] * (Cx[0][0] * A[Xc[0][0]] + Cx[0][1] * A[Xc[0][1]]
                              + Cx[0][2] * A[Xc[0][2]] + Cx[0][3] * A[Xc[0][3]]);
        }
        // chunk 1: bins 32..48 (lanes >= 17 compute a duplicate of bin 0)
        #pragma unroll
        for (int i = 0; i < 4; i++) {
            const float* A = fp + Ry[1][i];
            acc1 += Cy[1][i] * (Cx[1][0] * A[Xc[1][0]] + Cx[1][1] * A[Xc[1][1]]
                              + Cx[1][2] * A[Xc[1][2]] + Cx[1][3] * A[Xc[1][3]]);
        }

        op[lane] = acc0;
        if (lane < 17) op[32 + lane] = acc1;

        fp += plane;
        op += 49;
    }
}

extern "C" void kernel_launch(void* const* d_in, const int* in_sizes, int n_in,
                              void* d_out, int out_size) {
    const int nroi = in_sizes[4] / 4;   // 512
    roi_align_kernel<<<nroi, 256>>>(
        (const float*)d_in[0], (const float*)d_in[1],
        (const float*)d_in[2], (const float*)d_in[3],
        (const float*)d_in[4], (float*)d_out);
}